// round 11
// baseline (speedup 1.0000x reference)
#include <cuda_runtime.h>
#include <cuda_fp16.h>
#include <math.h>
#include <stdint.h>

#define B_SZ 256
#define DIM 2048
#define NH 8
#define HD 256
#define EPS 1e-5f

// ---------------- scratch (device globals; no allocation allowed) ----------
__device__ float g_qv[B_SZ * 2 * DIM];
__device__ float g_k1[B_SZ * DIM];
__device__ float g_k2n[B_SZ * DIM];
__device__ __half g_Ah[B_SZ * DIM];      // f_ad fp16
__device__ __half g_Ph[B_SZ * DIM];      // pooled fp16

// ---------------- helpers ----------------
__device__ __forceinline__ float warp_sum(float v) {
    v += __shfl_xor_sync(0xffffffffu, v, 16);
    v += __shfl_xor_sync(0xffffffffu, v, 8);
    v += __shfl_xor_sync(0xffffffffu, v, 4);
    v += __shfl_xor_sync(0xffffffffu, v, 2);
    v += __shfl_xor_sync(0xffffffffu, v, 1);
    return v;
}

__device__ __forceinline__ float gelu_tanh(float x) {
    const float k = 0.7978845608028654f;
    float x3 = x * x * x;
    return 0.5f * x * (1.0f + tanhf(k * (x + 0.044715f * x3)));
}

__device__ __forceinline__ uint32_t smem_u32(const void* p) {
    uint32_t a;
    asm("{ .reg .u64 t; cvta.to.shared.u64 t, %1; cvt.u32.u64 %0, t; }" : "=r"(a) : "l"(p));
    return a;
}

__device__ __forceinline__ void cpa16(uint32_t dst, const void* src) {
    asm volatile("cp.async.cg.shared.global [%0], [%1], 16;" :: "r"(dst), "l"(src));
}
#define CP_COMMIT() asm volatile("cp.async.commit_group;" ::: "memory")
#define CP_WAIT3()  asm volatile("cp.async.wait_group 3;" ::: "memory")

__device__ __forceinline__ uint32_t pack2h(float a, float b) {
    __half2 h = __floats2half2_rn(a, b);
    return *(uint32_t*)&h;
}

// fp16 mma: D(16x8,f32) += A(16x16,f16) * B(16x8,f16)
__device__ __forceinline__ void mma16816f(float* d, const uint32_t* a, const uint32_t* b) {
    asm volatile(
        "mma.sync.aligned.m16n8k16.row.col.f32.f16.f16.f32 "
        "{%0,%1,%2,%3}, {%4,%5,%6,%7}, {%8,%9}, {%0,%1,%2,%3};"
        : "+f"(d[0]), "+f"(d[1]), "+f"(d[2]), "+f"(d[3])
        : "r"(a[0]), "r"(a[1]), "r"(a[2]), "r"(a[3]), "r"(b[0]), "r"(b[1]));
}

// ---------------- 1a) prep: coalesced pool + AGF (null stream) -------------
#define NB_POOL 8192
#define NB_AGF  256
#define NB_PA (NB_POOL + NB_AGF)

__global__ void prep_pool_agf(const float* __restrict__ mem,
                              const float* __restrict__ f_age, const float* __restrict__ age_gap,
                              const float* __restrict__ rW, const float* __restrict__ rb,
                              const float* __restrict__ eW, const float* __restrict__ eb,
                              const float* __restrict__ lw, const float* __restrict__ lb,
                              __half* __restrict__ Ph, float* __restrict__ k2n) {
    __shared__ float srow[DIM];
    __shared__ float pr[8];
    int bx = blockIdx.x;
    int t = threadIdx.x, wid = t >> 5, lane = t & 31;

    if (bx < NB_POOL) {
        int gwarp = bx * 8 + wid;
        const float4* p = (const float4*)mem + (size_t)gwarp * 128;
        float s[4];
        #pragma unroll
        for (int i = 0; i < 4; i++) {
            float4 v = p[i * 32 + lane];           // fully coalesced 512B per instr
            s[i] = (v.x + v.y) + (v.z + v.w);
        }
        #pragma unroll
        for (int i = 0; i < 4; i++) {
            s[i] += __shfl_xor_sync(0xffffffffu, s[i], 1);
            s[i] += __shfl_xor_sync(0xffffffffu, s[i], 2);
            s[i] += __shfl_xor_sync(0xffffffffu, s[i], 4);
            s[i] += __shfl_xor_sync(0xffffffffu, s[i], 8);
        }
        int half = lane >> 4;
        if ((lane & 15) == 0) {
            #pragma unroll
            for (int i = 0; i < 4; i++)
                Ph[gwarp * 8 + 2 * i + half] = __float2half_rn(s[i] * (1.0f / 64.0f));
        }
        return;
    }
    // AGF branch + per-head LN -> k2_norm; one block per batch row
    int b = bx - NB_POOL;

    float part = 0.f;
    for (int i = t; i < DIM; i += 256) part += f_age[(size_t)b * DIM + i] * rW[i];
    part = warp_sum(part);
    if (lane == 0) pr[wid] = part;
    __syncthreads();
    float red = rb[0];
    #pragma unroll
    for (int i = 0; i < 8; i++) red += pr[i];
    float ag = age_gap[b];

    for (int i = t; i < DIM; i += 256) {
        srow[i] = f_age[(size_t)b * DIM + i] + eW[i * 2 + 0] * red + eW[i * 2 + 1] * ag + eb[i];
    }
    __syncthreads();

    float x[8], s = 0.f, ss = 0.f;
    #pragma unroll
    for (int j = 0; j < 8; j++) {
        x[j] = srow[wid * HD + lane + 32 * j];
        s += x[j]; ss += x[j] * x[j];
    }
    s = warp_sum(s); ss = warp_sum(ss);
    float mu = s * (1.0f / HD);
    float inv = rsqrtf(ss * (1.0f / HD) - mu * mu + EPS);
    #pragma unroll
    for (int j = 0; j < 8; j++) {
        int i = lane + 32 * j;
        k2n[(size_t)b * DIM + wid * HD + i] = (x[j] - mu) * inv * lw[i] + lb[i];
    }
}

// ---------------- 1b) prep: f_ad fp32 -> fp16 (side stream) ----------------
__global__ void prep_fad(const float4* __restrict__ f_ad, __half* __restrict__ Ah) {
    int i0 = blockIdx.x * 1024 + threadIdx.x;
    #pragma unroll
    for (int k = 0; k < 4; k++) {
        int i = i0 + k * 256;
        float4 v = f_ad[i];
        uint2 hp;
        hp.x = pack2h(v.x, v.y);
        hp.y = pack2h(v.z, v.w);
        ((uint2*)Ah)[i] = hp;
    }
}

// ---------------- 2) GEMM: A fp16 cp.async 4-stage; B fp32->fp16 coalesced -
// C[m,n] = sum_k A[m,k]*W[n,k]  (fp32 accum). CTA 128x128, K chunks of 64.
// grid.x = ntile within THIS weight matrix, grid.y = mtile.
#define CHUNKS 32
#define PITCH 144                       // 128B data + 16B pad
#define TILEB (128 * PITCH)             // 18432
#define NASTAGE 4
#define NBSTAGE 2
#define SMEM_B_OFF (NASTAGE * TILEB)    // 73728
#define GEMM_SMEM (NASTAGE * TILEB + NBSTAGE * TILEB)   // 110592

__global__ void __launch_bounds__(256, 1)
gemm_tc(const __half* __restrict__ A, const float* __restrict__ W,
        float* __restrict__ C, int ldc) {
    extern __shared__ char sm[];
    uint32_t sb = smem_u32(sm);
    int tid = threadIdx.x, wid = tid >> 5, lane = tid & 31;
    int ntile = blockIdx.x, mtile = blockIdx.y;
    int ncol0 = ntile * 128;
    const float* Wsrc = W + (size_t)ntile * 128 * DIM;

    // A loader role: row r, half qp of the 128B fp16 chunk row
    int r = tid >> 1, qp = tid & 1;
    const char* sA = (const char*)(A + (size_t)(mtile * 128 + r) * DIM) + qp * 64;
    uint32_t da = sb + r * PITCH + qp * 64;

    // B loader role: coalesced, 8 float4/thread
    int seg = tid & 15, rb0 = tid >> 4;
    const float4* Wf4 = (const float4*)Wsrc;
    uint32_t dbB[8];
    #pragma unroll
    for (int i = 0; i < 8; i++)
        dbB[i] = sb + SMEM_B_OFF + (uint32_t)(rb0 + 16 * i) * PITCH + seg * 8;

    // compute role
    int warp_m = wid >> 2, warp_n = wid & 3;
    int g = lane >> 2, tig = lane & 3;
    float acc[4][4][4] = {};
    uint32_t fA = sb + (warp_m * 64 + g) * PITCH + tig * 4;
    uint32_t fB0 = sb + SMEM_B_OFF + (warp_n * 32 + g) * PITCH + tig * 4;

    // prologue
    float4 b4[8];
    #pragma unroll
    for (int i = 0; i < 8; i++)
        b4[i] = Wf4[(size_t)(rb0 + 16 * i) * 512 + seg];
    #pragma unroll
    for (int s = 0; s < NASTAGE; s++) {
        uint32_t d = da + s * TILEB;
        const char* pa = sA + s * 128;
        cpa16(d, pa); cpa16(d + 16, pa + 16);
        cpa16(d + 32, pa + 32); cpa16(d + 48, pa + 48);
        CP_COMMIT();
    }

    for (int c = 0; c < CHUNKS; ++c) {
        uint32_t soA = (uint32_t)(c & (NASTAGE - 1)) * TILEB;
        uint32_t soB = (uint32_t)(c & 1) * TILEB;
        CP_WAIT3();
        #pragma unroll
        for (int i = 0; i < 8; i++) {
            uint32_t p0 = pack2h(b4[i].x, b4[i].y);
            uint32_t p1 = pack2h(b4[i].z, b4[i].w);
            asm volatile("st.shared.v2.b32 [%0], {%1,%2};"
                         :: "r"(dbB[i] + soB), "r"(p0), "r"(p1));
        }
        __syncthreads();
        if (c + 1 < CHUNKS) {
            #pragma unroll
            for (int i = 0; i < 8; i++)
                b4[i] = Wf4[(size_t)(rb0 + 16 * i) * 512 + (c + 1) * 16 + seg];
        }

        #pragma unroll
        for (int ks = 0; ks < 4; ks++) {
            uint32_t kbA = soA + ks * 32;
            uint32_t kbB = soB + ks * 32;
            uint32_t Af[4][4], Bf[4][2];
            #pragma unroll
            for (int i = 0; i < 4; i++) {
                uint32_t ph = fA + i * 16 * PITCH + kbA;
                asm volatile("ld.shared.b32 %0, [%1];" : "=r"(Af[i][0]) : "r"(ph));
                asm volatile("ld.shared.b32 %0, [%1];" : "=r"(Af[i][1]) : "r"(ph + 8 * PITCH));
                asm volatile("ld.shared.b32 %0, [%1];" : "=r"(Af[i][2]) : "r"(ph + 16));
                asm volatile("ld.shared.b32 %0, [%1];" : "=r"(Af[i][3]) : "r"(ph + 8 * PITCH + 16));
            }
            #pragma unroll
            for (int j = 0; j < 4; j++) {
                uint32_t ph = fB0 + j * 8 * PITCH + kbB;
                asm volatile("ld.shared.b32 %0, [%1];" : "=r"(Bf[j][0]) : "r"(ph));
                asm volatile("ld.shared.b32 %0, [%1];" : "=r"(Bf[j][1]) : "r"(ph + 16));
            }
            #pragma unroll
            for (int i = 0; i < 4; i++)
                #pragma unroll
                for (int j = 0; j < 4; j++)
                    mma16816f(acc[i][j], Af[i], Bf[j]);
        }
        __syncthreads();

        int cn = c + NASTAGE;
        if (cn < CHUNKS) {
            uint32_t d = da + soA;
            const char* pa = sA + cn * 128;
            cpa16(d, pa); cpa16(d + 16, pa + 16);
            cpa16(d + 32, pa + 32); cpa16(d + 48, pa + 48);
        }
        CP_COMMIT();
    }

    // epilogue
    #pragma unroll
    for (int i = 0; i < 4; i++) {
        int r0 = mtile * 128 + warp_m * 64 + i * 16 + g;
        #pragma unroll
        for (int j = 0; j < 4; j++) {
            int col = ncol0 + warp_n * 32 + j * 8 + 2 * tig;
            *(float2*)&C[(size_t)r0 * ldc + col]       = make_float2(acc[i][j][0], acc[i][j][1]);
            *(float2*)&C[(size_t)(r0 + 8) * ldc + col] = make_float2(acc[i][j][2], acc[i][j][3]);
        }
    }
}

// ---------------- 3) fused: head-LN(q,k1) + 2x attn + 2x conv1d + LNs + GELUs
__global__ void __launch_bounds__(256, 4)
fused_attn(const float* __restrict__ qv, const float* __restrict__ k1,
           const float* __restrict__ k2n,
           const float* __restrict__ lw, const float* __restrict__ lb,
           const float* __restrict__ l2w, const float* __restrict__ l2b,
           const float* __restrict__ w1, const float* __restrict__ w2,
           float* __restrict__ out) {
    __shared__ float sQ[DIM], sK1[DIM], sK2[DIM], sV[DIM], sO1[DIM];
    __shared__ float cw1[192], cw2[192];
    __shared__ float rs[8], rss[8];
    float* sO2 = sK1;

    int b = blockIdx.x, t = threadIdx.x;
    int wid = t >> 5, lane = t & 31;

    {
        float x[8], s = 0.f, ss = 0.f;
        #pragma unroll
        for (int j = 0; j < 8; j++) {
            x[j] = qv[(size_t)b * 2 * DIM + wid * HD + lane + 32 * j];
            s += x[j]; ss += x[j] * x[j];
        }
        s = warp_sum(s); ss = warp_sum(ss);
        float mu = s * (1.0f / HD), inv = rsqrtf(ss * (1.0f / HD) - mu * mu + EPS);
        #pragma unroll
        for (int j = 0; j < 8; j++) {
            int i = lane + 32 * j;
            sQ[wid * HD + i] = (x[j] - mu) * inv * lw[i] + lb[i];
        }
    }
    {
        float x[8], s = 0.f, ss = 0.f;
        #pragma unroll
        for (int j = 0; j < 8; j++) {
            x[j] = k1[(size_t)b * DIM + wid * HD + lane + 32 * j];
            s += x[j]; ss += x[j] * x[j];
        }
        s = warp_sum(s); ss = warp_sum(ss);
        float mu = s * (1.0f / HD), inv = rsqrtf(ss * (1.0f / HD) - mu * mu + EPS);
        #pragma unroll
        for (int j = 0; j < 8; j++) {
            int i = lane + 32 * j;
            sK1[wid * HD + i] = (x[j] - mu) * inv * lw[i] + lb[i];
        }
    }
    for (int i = t; i < DIM; i += 256) {
        sK2[i] = k2n[(size_t)b * DIM + i];
        sV[i]  = qv[(size_t)b * 2 * DIM + DIM + i];
    }
    if (t < 192) { cw1[t] = w1[t]; cw2[t] = w2[t]; }
    __syncthreads();

    {
        float a[8];
        #pragma unroll
        for (int s = 0; s < 8; s++) {
            float p = 0.f;
            #pragma unroll
            for (int j = 0; j < 8; j++)
                p = fmaf(sQ[wid * HD + lane + 32 * j], sK1[s * HD + lane + 32 * j], p);
            a[s] = warp_sum(p) * (1.0f / 16.0f);
        }
        float m = a[0];
        #pragma unroll
        for (int s = 1; s < 8; s++) m = fmaxf(m, a[s]);
        float sum = 0.f;
        #pragma unroll
        for (int s = 0; s < 8; s++) { a[s] = expf(a[s] - m); sum += a[s]; }
        float inv = 1.0f / sum;
        #pragma unroll
        for (int j = 0; j < 8; j++) {
            int cc = lane + 32 * j;
            float acc = 0.f;
            #pragma unroll
            for (int s = 0; s < 8; s++) acc = fmaf(a[s], sV[s * HD + cc], acc);
            sO1[wid * HD + cc] = acc * inv;
        }
    }
    __syncthreads();

    {
        float a[8];
        #pragma unroll
        for (int s = 0; s < 8; s++) {
            float p = 0.f;
            #pragma unroll
            for (int j = 0; j < 8; j++)
                p = fmaf(sQ[wid * HD + lane + 32 * j], sK2[s * HD + lane + 32 * j], p);
            a[s] = warp_sum(p) * (1.0f / 16.0f);
        }
        float m = a[0];
        #pragma unroll
        for (int s = 1; s < 8; s++) m = fmaxf(m, a[s]);
        float sum = 0.f;
        #pragma unroll
        for (int s = 0; s < 8; s++) { a[s] = expf(a[s] - m); sum += a[s]; }
        float inv = 1.0f / sum;
        #pragma unroll
        for (int j = 0; j < 8; j++) {
            int cc = lane + 32 * j;
            float acc = 0.f;
            #pragma unroll
            for (int s = 0; s < 8; s++) acc = fmaf(a[s], sV[s * HD + cc], acc);
            sO2[wid * HD + cc] = acc * inv;
        }
    }
    __syncthreads();

    float c1[8], c2[8], g[8];
    #pragma unroll
    for (int j = 0; j < 8; j++) {
        int l = lane + 32 * j;
        float a1 = 0.f, a2 = 0.f;
        #pragma unroll
        for (int i = 0; i < 8; i++) {
            float xm = (l > 0)   ? sO1[i * HD + l - 1] : 0.f;
            float x0 =             sO1[i * HD + l];
            float xp = (l < 255) ? sO1[i * HD + l + 1] : 0.f;
            a1 = fmaf(cw1[wid * 24 + i * 3 + 0], xm, a1);
            a1 = fmaf(cw1[wid * 24 + i * 3 + 1], x0, a1);
            a1 = fmaf(cw1[wid * 24 + i * 3 + 2], xp, a1);
            float ym = (l > 0)   ? sO2[i * HD + l - 1] : 0.f;
            float y0 =             sO2[i * HD + l];
            float yp = (l < 255) ? sO2[i * HD + l + 1] : 0.f;
            a2 = fmaf(cw2[wid * 24 + i * 3 + 0], ym, a2);
            a2 = fmaf(cw2[wid * 24 + i * 3 + 1], y0, a2);
            a2 = fmaf(cw2[wid * 24 + i * 3 + 2], yp, a2);
        }
        c1[j] = a1; c2[j] = a2;
    }

    {
        float s = 0.f, ss = 0.f;
        #pragma unroll
        for (int j = 0; j < 8; j++) { s += c1[j]; ss += c1[j] * c1[j]; }
        s = warp_sum(s); ss = warp_sum(ss);
        float mu = s * (1.0f / HD), inv = rsqrtf(ss * (1.0f / HD) - mu * mu + EPS);
        #pragma unroll
        for (int j = 0; j < 8; j++) { int i = lane + 32 * j; c1[j] = (c1[j] - mu) * inv * lw[i] + lb[i]; }
    }
    {
        float s = 0.f, ss = 0.f;
        #pragma unroll
        for (int j = 0; j < 8; j++) { s += c2[j]; ss += c2[j] * c2[j]; }
        s = warp_sum(s); ss = warp_sum(ss);
        float mu = s * (1.0f / HD), inv = rsqrtf(ss * (1.0f / HD) - mu * mu + EPS);
        #pragma unroll
        for (int j = 0; j < 8; j++) { int i = lane + 32 * j; c2[j] = (c2[j] - mu) * inv * lw[i] + lb[i]; }
    }
    {
        float x[8], s = 0.f, ss = 0.f;
        #pragma unroll
        for (int j = 0; j < 8; j++) {
            x[j] = c1[j] + c2[j] + sV[wid * HD + lane + 32 * j];
            s += x[j]; ss += x[j] * x[j];
        }
        s = warp_sum(s); ss = warp_sum(ss);
        float mu = s * (1.0f / HD), inv = rsqrtf(ss * (1.0f / HD) - mu * mu + EPS);
        #pragma unroll
        for (int j = 0; j < 8; j++) {
            int i = lane + 32 * j;
            g[j] = gelu_tanh((x[j] - mu) * inv * lw[i] + lb[i]);
        }
    }
    {
        float s = 0.f, ss = 0.f;
        #pragma unroll
        for (int j = 0; j < 8; j++) { s += g[j]; ss += g[j] * g[j]; }
        s = warp_sum(s); ss = warp_sum(ss);
        if (lane == 0) { rs[wid] = s; rss[wid] = ss; }
        __syncthreads();
        float ts = 0.f, tss = 0.f;
        #pragma unroll
        for (int i = 0; i < 8; i++) { ts += rs[i]; tss += rss[i]; }
        float mu = ts * (1.0f / DIM), inv = rsqrtf(tss * (1.0f / DIM) - mu * mu + EPS);
        #pragma unroll
        for (int j = 0; j < 8; j++) {
            int idx = wid * HD + lane + 32 * j;
            float y = (g[j] - mu) * inv * l2w[idx] + l2b[idx];
            out[(size_t)b * DIM + idx] = gelu_tanh(y);
        }
    }
}

// ---------------- launch ----------------
extern "C" void kernel_launch(void* const* d_in, const int* in_sizes, int n_in,
                              void* d_out, int out_size) {
    const float* f_ad    = (const float*)d_in[0];
    const float* f_age   = (const float*)d_in[1];
    const float* mem     = (const float*)d_in[2];
    const float* age_gap = (const float*)d_in[3];
    const float* qv_W    = (const float*)d_in[4];
    const float* k1_W    = (const float*)d_in[5];
    // d_in[6] = k2_W : dead in the reference — skipped
    const float* ln_w    = (const float*)d_in[7];
    const float* ln_b    = (const float*)d_in[8];
    const float* ln2_w   = (const float*)d_in[9];
    const float* ln2_b   = (const float*)d_in[10];
    const float* agf_rW  = (const float*)d_in[11];
    const float* agf_rb  = (const float*)d_in[12];
    const float* agf_eW  = (const float*)d_in[13];
    const float* agf_eb  = (const float*)d_in[14];
    const float* c1W     = (const float*)d_in[15];
    const float* c2W     = (const float*)d_in[16];
    float* out = (float*)d_out;

    float *qvb, *k1b, *k2n;
    __half *Ahp, *Php;
    cudaGetSymbolAddress((void**)&qvb, g_qv);
    cudaGetSymbolAddress((void**)&k1b, g_k1);
    cudaGetSymbolAddress((void**)&k2n, g_k2n);
    cudaGetSymbolAddress((void**)&Ahp, g_Ah);
    cudaGetSymbolAddress((void**)&Php, g_Ph);

    static cudaStream_t s2 = nullptr;
    static cudaEvent_t evF = nullptr, evJ = nullptr;
    if (s2 == nullptr) {
        cudaStreamCreateWithFlags(&s2, cudaStreamNonBlocking);
        cudaEventCreateWithFlags(&evF, cudaEventDisableTiming);
        cudaEventCreateWithFlags(&evJ, cudaEventDisableTiming);
        cudaFuncSetAttribute(gemm_tc, cudaFuncAttributeMaxDynamicSharedMemorySize, GEMM_SMEM);
    }

    // fork: side stream branches from the main (capture) stream at t=0
    cudaEventRecord(evF, 0);
    cudaStreamWaitEvent(s2, evF, 0);

    // side stream: f_ad convert -> qv GEMM (independent of pool)
    prep_fad<<<128, 256, 0, s2>>>((const float4*)f_ad, Ahp);
    gemm_tc<<<dim3(32, 2), 256, GEMM_SMEM, s2>>>(Ahp, qv_W, qvb, 2 * DIM);
    cudaEventRecord(evJ, s2);

    // main stream: pool + AGF -> k1 GEMM
    prep_pool_agf<<<NB_PA, 256>>>(mem, f_age, age_gap,
                                  agf_rW, agf_rb, agf_eW, agf_eb, ln_w, ln_b,
                                  Php, k2n);
    gemm_tc<<<dim3(16, 2), 256, GEMM_SMEM>>>(Php, k1_W, k1b, DIM);

    // join: attn needs qv (side stream) + k1/k2n (main stream)
    cudaStreamWaitEvent(0, evJ, 0);
    fused_attn<<<B_SZ, 256>>>(qvb, k1b, k2n, ln_w, ln_b, ln2_w, ln2_b, c1W, c2W, out);
}

// round 12
// speedup vs baseline: 1.0740x; 1.0740x over previous
#include <cuda_runtime.h>
#include <cuda_fp16.h>
#include <math.h>
#include <stdint.h>

#define B_SZ 256
#define DIM 2048
#define NH 8
#define HD 256
#define EPS 1e-5f

// ---------------- scratch (device globals; no allocation allowed) ----------
__device__ float g_qv[B_SZ * 2 * DIM];
__device__ float g_k1[B_SZ * DIM];
__device__ float g_k2n[B_SZ * DIM];
__device__ __half g_Ah[B_SZ * DIM];      // f_ad fp16
__device__ __half g_Ph[B_SZ * DIM];      // pooled fp16

// ---------------- helpers ----------------
__device__ __forceinline__ float warp_sum(float v) {
    v += __shfl_xor_sync(0xffffffffu, v, 16);
    v += __shfl_xor_sync(0xffffffffu, v, 8);
    v += __shfl_xor_sync(0xffffffffu, v, 4);
    v += __shfl_xor_sync(0xffffffffu, v, 2);
    v += __shfl_xor_sync(0xffffffffu, v, 1);
    return v;
}

__device__ __forceinline__ float gelu_tanh(float x) {
    const float k = 0.7978845608028654f;
    float x3 = x * x * x;
    return 0.5f * x * (1.0f + tanhf(k * (x + 0.044715f * x3)));
}

__device__ __forceinline__ uint32_t smem_u32(const void* p) {
    uint32_t a;
    asm("{ .reg .u64 t; cvta.to.shared.u64 t, %1; cvt.u32.u64 %0, t; }" : "=r"(a) : "l"(p));
    return a;
}

__device__ __forceinline__ void cpa16(uint32_t dst, const void* src) {
    asm volatile("cp.async.cg.shared.global [%0], [%1], 16;" :: "r"(dst), "l"(src));
}
#define CP_COMMIT() asm volatile("cp.async.commit_group;" ::: "memory")
#define CP_WAIT3()  asm volatile("cp.async.wait_group 3;" ::: "memory")

__device__ __forceinline__ uint32_t pack2h(float a, float b) {
    __half2 h = __floats2half2_rn(a, b);
    return *(uint32_t*)&h;
}

// fp16 mma: D(16x8,f32) += A(16x16,f16) * B(16x8,f16)
__device__ __forceinline__ void mma16816f(float* d, const uint32_t* a, const uint32_t* b) {
    asm volatile(
        "mma.sync.aligned.m16n8k16.row.col.f32.f16.f16.f32 "
        "{%0,%1,%2,%3}, {%4,%5,%6,%7}, {%8,%9}, {%0,%1,%2,%3};"
        : "+f"(d[0]), "+f"(d[1]), "+f"(d[2]), "+f"(d[3])
        : "r"(a[0]), "r"(a[1]), "r"(a[2]), "r"(a[3]), "r"(b[0]), "r"(b[1]));
}

// ---------------- 1) prep: coalesced pool + f_ad cvt + AGF -----------------
#define NB_POOL 8192
#define NB_FAD  128
#define NB_AGF  256
#define NB_PREP (NB_POOL + NB_FAD + NB_AGF)

__global__ void prep_kernel(const float* __restrict__ mem,
                            const float4* __restrict__ f_ad,
                            const float* __restrict__ f_age, const float* __restrict__ age_gap,
                            const float* __restrict__ rW, const float* __restrict__ rb,
                            const float* __restrict__ eW, const float* __restrict__ eb,
                            const float* __restrict__ lw, const float* __restrict__ lb,
                            __half* __restrict__ Ph, __half* __restrict__ Ah,
                            float* __restrict__ k2n) {
    __shared__ float srow[DIM];
    __shared__ float pr[8];
    int bx = blockIdx.x;
    int t = threadIdx.x, wid = t >> 5, lane = t & 31;

    if (bx < NB_POOL) {
        int gwarp = bx * 8 + wid;
        const float4* p = (const float4*)mem + (size_t)gwarp * 128;
        float s[4];
        #pragma unroll
        for (int i = 0; i < 4; i++) {
            float4 v = p[i * 32 + lane];           // fully coalesced 512B per instr
            s[i] = (v.x + v.y) + (v.z + v.w);
        }
        #pragma unroll
        for (int i = 0; i < 4; i++) {
            s[i] += __shfl_xor_sync(0xffffffffu, s[i], 1);
            s[i] += __shfl_xor_sync(0xffffffffu, s[i], 2);
            s[i] += __shfl_xor_sync(0xffffffffu, s[i], 4);
            s[i] += __shfl_xor_sync(0xffffffffu, s[i], 8);
        }
        int half = lane >> 4;
        if ((lane & 15) == 0) {
            #pragma unroll
            for (int i = 0; i < 4; i++)
                Ph[gwarp * 8 + 2 * i + half] = __float2half_rn(s[i] * (1.0f / 64.0f));
        }
        return;
    }
    bx -= NB_POOL;
    if (bx < NB_FAD) {
        int i0 = bx * 1024 + t;
        #pragma unroll
        for (int k = 0; k < 4; k++) {
            int i = i0 + k * 256;
            float4 v = f_ad[i];
            uint2 hp;
            hp.x = pack2h(v.x, v.y);
            hp.y = pack2h(v.z, v.w);
            ((uint2*)Ah)[i] = hp;
        }
        return;
    }
    // AGF branch + per-head LN -> k2_norm; one block per batch row
    int b = bx - NB_FAD;

    float part = 0.f;
    for (int i = t; i < DIM; i += 256) part += f_age[(size_t)b * DIM + i] * rW[i];
    part = warp_sum(part);
    if (lane == 0) pr[wid] = part;
    __syncthreads();
    float red = rb[0];
    #pragma unroll
    for (int i = 0; i < 8; i++) red += pr[i];
    float ag = age_gap[b];

    for (int i = t; i < DIM; i += 256) {
        srow[i] = f_age[(size_t)b * DIM + i] + eW[i * 2 + 0] * red + eW[i * 2 + 1] * ag + eb[i];
    }
    __syncthreads();

    float x[8], s = 0.f, ss = 0.f;
    #pragma unroll
    for (int j = 0; j < 8; j++) {
        x[j] = srow[wid * HD + lane + 32 * j];
        s += x[j]; ss += x[j] * x[j];
    }
    s = warp_sum(s); ss = warp_sum(ss);
    float mu = s * (1.0f / HD);
    float inv = rsqrtf(ss * (1.0f / HD) - mu * mu + EPS);
    #pragma unroll
    for (int j = 0; j < 8; j++) {
        int i = lane + 32 * j;
        k2n[(size_t)b * DIM + wid * HD + i] = (x[j] - mu) * inv * lw[i] + lb[i];
    }
}

// ---------------- 2) GEMM: 512 threads / 16 warps, A cp.async, B in-loader -
// C[m,n] = sum_k A[m,k]*W[n,k]  (fp32 accum). CTA 128x128, K chunks of 64.
// 16 warps in 4x4; warp tile 32x32 (2 m-frags x 4 n-frags).
#define CHUNKS 32
#define PITCH 144                       // 128B data + 16B pad
#define TILEB (128 * PITCH)             // 18432
#define NASTAGE 4
#define NBSTAGE 2
#define SMEM_B_OFF (NASTAGE * TILEB)    // 73728
#define GEMM_SMEM (NASTAGE * TILEB + NBSTAGE * TILEB)   // 110592

__global__ void __launch_bounds__(512, 1)
gemm_tc(const __half* __restrict__ Ah, const __half* __restrict__ Ph,
        const float* __restrict__ Wqv, const float* __restrict__ Wk1,
        float* __restrict__ Cqv, float* __restrict__ Ck1) {
    extern __shared__ char sm[];
    uint32_t sb = smem_u32(sm);
    int tid = threadIdx.x, wid = tid >> 5, lane = tid & 31;
    int ntile = blockIdx.x, mtile = blockIdx.y;

    bool is_qv = ntile < 32;
    const __half* a;
    const float* Wsrc;
    float* C;
    int ldc, ncol0;
    if (is_qv) {
        a = Ah; Wsrc = Wqv + (size_t)ntile * 128 * DIM;
        C = Cqv; ldc = 2 * DIM; ncol0 = ntile * 128;
    } else {
        a = Ph; Wsrc = Wk1 + (size_t)(ntile - 32) * 128 * DIM;
        C = Ck1; ldc = DIM; ncol0 = (ntile - 32) * 128;
    }

    // A loader role: row r (4 threads/row), 32B segment q
    int r = tid >> 2, q = (tid & 3) * 32;
    const char* sA = (const char*)(a + (size_t)(mtile * 128 + r) * DIM) + q;
    uint32_t da = sb + r * PITCH + q;

    // B loader role: coalesced, 4 float4/thread (chunk = 128 rows x 64 fp32)
    int seg = tid & 15, rb0 = tid >> 4;   // rb0 in 0..31
    const float4* Wf4 = (const float4*)Wsrc;
    uint32_t dbB[4];
    #pragma unroll
    for (int i = 0; i < 4; i++)
        dbB[i] = sb + SMEM_B_OFF + (uint32_t)(rb0 + 32 * i) * PITCH + seg * 8;

    // compute role: 16 warps 4x4, warp tile 32x32
    int warp_m = wid >> 2, warp_n = wid & 3;
    int g = lane >> 2, tig = lane & 3;
    float acc[2][4][4] = {};
    uint32_t fA = sb + (warp_m * 32 + g) * PITCH + tig * 4;
    uint32_t fB0 = sb + SMEM_B_OFF + (warp_n * 32 + g) * PITCH + tig * 4;

    // prologue: B chunk 0 into regs; A stages 0..3 via cp.async
    float4 b4[4];
    #pragma unroll
    for (int i = 0; i < 4; i++)
        b4[i] = Wf4[(size_t)(rb0 + 32 * i) * 512 + seg];
    #pragma unroll
    for (int s = 0; s < NASTAGE; s++) {
        uint32_t d = da + s * TILEB;
        const char* pa = sA + s * 128;
        cpa16(d, pa); cpa16(d + 16, pa + 16);
        CP_COMMIT();
    }

    for (int c = 0; c < CHUNKS; ++c) {
        uint32_t soA = (uint32_t)(c & (NASTAGE - 1)) * TILEB;
        uint32_t soB = (uint32_t)(c & 1) * TILEB;
        CP_WAIT3();
        // pack + STS B(c) (conflict-free 64-bit stores)
        #pragma unroll
        for (int i = 0; i < 4; i++) {
            uint32_t p0 = pack2h(b4[i].x, b4[i].y);
            uint32_t p1 = pack2h(b4[i].z, b4[i].w);
            asm volatile("st.shared.v2.b32 [%0], {%1,%2};"
                         :: "r"(dbB[i] + soB), "r"(p0), "r"(p1));
        }
        __syncthreads();
        // prefetch B(c+1) coalesced
        if (c + 1 < CHUNKS) {
            #pragma unroll
            for (int i = 0; i < 4; i++)
                b4[i] = Wf4[(size_t)(rb0 + 32 * i) * 512 + (c + 1) * 16 + seg];
        }

        #pragma unroll
        for (int ks = 0; ks < 4; ks++) {
            uint32_t kbA = soA + ks * 32;
            uint32_t kbB = soB + ks * 32;
            uint32_t Af[2][4], Bf[4][2];
            #pragma unroll
            for (int i = 0; i < 2; i++) {
                uint32_t ph = fA + i * 16 * PITCH + kbA;
                asm volatile("ld.shared.b32 %0, [%1];" : "=r"(Af[i][0]) : "r"(ph));
                asm volatile("ld.shared.b32 %0, [%1];" : "=r"(Af[i][1]) : "r"(ph + 8 * PITCH));
                asm volatile("ld.shared.b32 %0, [%1];" : "=r"(Af[i][2]) : "r"(ph + 16));
                asm volatile("ld.shared.b32 %0, [%1];" : "=r"(Af[i][3]) : "r"(ph + 8 * PITCH + 16));
            }
            #pragma unroll
            for (int j = 0; j < 4; j++) {
                uint32_t ph = fB0 + j * 8 * PITCH + kbB;
                asm volatile("ld.shared.b32 %0, [%1];" : "=r"(Bf[j][0]) : "r"(ph));
                asm volatile("ld.shared.b32 %0, [%1];" : "=r"(Bf[j][1]) : "r"(ph + 16));
            }
            #pragma unroll
            for (int i = 0; i < 2; i++)
                #pragma unroll
                for (int j = 0; j < 4; j++)
                    mma16816f(acc[i][j], Af[i], Bf[j]);
        }
        __syncthreads();

        int cn = c + NASTAGE;
        if (cn < CHUNKS) {
            uint32_t d = da + soA;
            const char* pa = sA + cn * 128;
            cpa16(d, pa); cpa16(d + 16, pa + 16);
        }
        CP_COMMIT();
    }

    // epilogue
    #pragma unroll
    for (int i = 0; i < 2; i++) {
        int r0 = mtile * 128 + warp_m * 32 + i * 16 + g;
        #pragma unroll
        for (int j = 0; j < 4; j++) {
            int col = ncol0 + warp_n * 32 + j * 8 + 2 * tig;
            *(float2*)&C[(size_t)r0 * ldc + col]       = make_float2(acc[i][j][0], acc[i][j][1]);
            *(float2*)&C[(size_t)(r0 + 8) * ldc + col] = make_float2(acc[i][j][2], acc[i][j][3]);
        }
    }
}

// ---------------- 3) fused: head-LN(q,k1) + 2x attn + 2x conv1d + LNs + GELUs
__global__ void __launch_bounds__(256, 4)
fused_attn(const float* __restrict__ qv, const float* __restrict__ k1,
           const float* __restrict__ k2n,
           const float* __restrict__ lw, const float* __restrict__ lb,
           const float* __restrict__ l2w, const float* __restrict__ l2b,
           const float* __restrict__ w1, const float* __restrict__ w2,
           float* __restrict__ out) {
    __shared__ float sQ[DIM], sK1[DIM], sK2[DIM], sV[DIM], sO1[DIM];
    __shared__ float cw1[192], cw2[192];
    __shared__ float rs[8], rss[8];
    float* sO2 = sK1;

    int b = blockIdx.x, t = threadIdx.x;
    int wid = t >> 5, lane = t & 31;

    {
        float x[8], s = 0.f, ss = 0.f;
        #pragma unroll
        for (int j = 0; j < 8; j++) {
            x[j] = qv[(size_t)b * 2 * DIM + wid * HD + lane + 32 * j];
            s += x[j]; ss += x[j] * x[j];
        }
        s = warp_sum(s); ss = warp_sum(ss);
        float mu = s * (1.0f / HD), inv = rsqrtf(ss * (1.0f / HD) - mu * mu + EPS);
        #pragma unroll
        for (int j = 0; j < 8; j++) {
            int i = lane + 32 * j;
            sQ[wid * HD + i] = (x[j] - mu) * inv * lw[i] + lb[i];
        }
    }
    {
        float x[8], s = 0.f, ss = 0.f;
        #pragma unroll
        for (int j = 0; j < 8; j++) {
            x[j] = k1[(size_t)b * DIM + wid * HD + lane + 32 * j];
            s += x[j]; ss += x[j] * x[j];
        }
        s = warp_sum(s); ss = warp_sum(ss);
        float mu = s * (1.0f / HD), inv = rsqrtf(ss * (1.0f / HD) - mu * mu + EPS);
        #pragma unroll
        for (int j = 0; j < 8; j++) {
            int i = lane + 32 * j;
            sK1[wid * HD + i] = (x[j] - mu) * inv * lw[i] + lb[i];
        }
    }
    for (int i = t; i < DIM; i += 256) {
        sK2[i] = k2n[(size_t)b * DIM + i];
        sV[i]  = qv[(size_t)b * 2 * DIM + DIM + i];
    }
    if (t < 192) { cw1[t] = w1[t]; cw2[t] = w2[t]; }
    __syncthreads();

    {
        float a[8];
        #pragma unroll
        for (int s = 0; s < 8; s++) {
            float p = 0.f;
            #pragma unroll
            for (int j = 0; j < 8; j++)
                p = fmaf(sQ[wid * HD + lane + 32 * j], sK1[s * HD + lane + 32 * j], p);
            a[s] = warp_sum(p) * (1.0f / 16.0f);
        }
        float m = a[0];
        #pragma unroll
        for (int s = 1; s < 8; s++) m = fmaxf(m, a[s]);
        float sum = 0.f;
        #pragma unroll
        for (int s = 0; s < 8; s++) { a[s] = expf(a[s] - m); sum += a[s]; }
        float inv = 1.0f / sum;
        #pragma unroll
        for (int j = 0; j < 8; j++) {
            int cc = lane + 32 * j;
            float acc = 0.f;
            #pragma unroll
            for (int s = 0; s < 8; s++) acc = fmaf(a[s], sV[s * HD + cc], acc);
            sO1[wid * HD + cc] = acc * inv;
        }
    }
    __syncthreads();

    {
        float a[8];
        #pragma unroll
        for (int s = 0; s < 8; s++) {
            float p = 0.f;
            #pragma unroll
            for (int j = 0; j < 8; j++)
                p = fmaf(sQ[wid * HD + lane + 32 * j], sK2[s * HD + lane + 32 * j], p);
            a[s] = warp_sum(p) * (1.0f / 16.0f);
        }
        float m = a[0];
        #pragma unroll
        for (int s = 1; s < 8; s++) m = fmaxf(m, a[s]);
        float sum = 0.f;
        #pragma unroll
        for (int s = 0; s < 8; s++) { a[s] = expf(a[s] - m); sum += a[s]; }
        float inv = 1.0f / sum;
        #pragma unroll
        for (int j = 0; j < 8; j++) {
            int cc = lane + 32 * j;
            float acc = 0.f;
            #pragma unroll
            for (int s = 0; s < 8; s++) acc = fmaf(a[s], sV[s * HD + cc], acc);
            sO2[wid * HD + cc] = acc * inv;
        }
    }
    __syncthreads();

    float c1[8], c2[8], g[8];
    #pragma unroll
    for (int j = 0; j < 8; j++) {
        int l = lane + 32 * j;
        float a1 = 0.f, a2 = 0.f;
        #pragma unroll
        for (int i = 0; i < 8; i++) {
            float xm = (l > 0)   ? sO1[i * HD + l - 1] : 0.f;
            float x0 =             sO1[i * HD + l];
            float xp = (l < 255) ? sO1[i * HD + l + 1] : 0.f;
            a1 = fmaf(cw1[wid * 24 + i * 3 + 0], xm, a1);
            a1 = fmaf(cw1[wid * 24 + i * 3 + 1], x0, a1);
            a1 = fmaf(cw1[wid * 24 + i * 3 + 2], xp, a1);
            float ym = (l > 0)   ? sO2[i * HD + l - 1] : 0.f;
            float y0 =             sO2[i * HD + l];
            float yp = (l < 255) ? sO2[i * HD + l + 1] : 0.f;
            a2 = fmaf(cw2[wid * 24 + i * 3 + 0], ym, a2);
            a2 = fmaf(cw2[wid * 24 + i * 3 + 1], y0, a2);
            a2 = fmaf(cw2[wid * 24 + i * 3 + 2], yp, a2);
        }
        c1[j] = a1; c2[j] = a2;
    }

    {
        float s = 0.f, ss = 0.f;
        #pragma unroll
        for (int j = 0; j < 8; j++) { s += c1[j]; ss += c1[j] * c1[j]; }
        s = warp_sum(s); ss = warp_sum(ss);
        float mu = s * (1.0f / HD), inv = rsqrtf(ss * (1.0f / HD) - mu * mu + EPS);
        #pragma unroll
        for (int j = 0; j < 8; j++) { int i = lane + 32 * j; c1[j] = (c1[j] - mu) * inv * lw[i] + lb[i]; }
    }
    {
        float s = 0.f, ss = 0.f;
        #pragma unroll
        for (int j = 0; j < 8; j++) { s += c2[j]; ss += c2[j] * c2[j]; }
        s = warp_sum(s); ss = warp_sum(ss);
        float mu = s * (1.0f / HD), inv = rsqrtf(ss * (1.0f / HD) - mu * mu + EPS);
        #pragma unroll
        for (int j = 0; j < 8; j++) { int i = lane + 32 * j; c2[j] = (c2[j] - mu) * inv * lw[i] + lb[i]; }
    }
    {
        float x[8], s = 0.f, ss = 0.f;
        #pragma unroll
        for (int j = 0; j < 8; j++) {
            x[j] = c1[j] + c2[j] + sV[wid * HD + lane + 32 * j];
            s += x[j]; ss += x[j] * x[j];
        }
        s = warp_sum(s); ss = warp_sum(ss);
        float mu = s * (1.0f / HD), inv = rsqrtf(ss * (1.0f / HD) - mu * mu + EPS);
        #pragma unroll
        for (int j = 0; j < 8; j++) {
            int i = lane + 32 * j;
            g[j] = gelu_tanh((x[j] - mu) * inv * lw[i] + lb[i]);
        }
    }
    {
        float s = 0.f, ss = 0.f;
        #pragma unroll
        for (int j = 0; j < 8; j++) { s += g[j]; ss += g[j] * g[j]; }
        s = warp_sum(s); ss = warp_sum(ss);
        if (lane == 0) { rs[wid] = s; rss[wid] = ss; }
        __syncthreads();
        float ts = 0.f, tss = 0.f;
        #pragma unroll
        for (int i = 0; i < 8; i++) { ts += rs[i]; tss += rss[i]; }
        float mu = ts * (1.0f / DIM), inv = rsqrtf(tss * (1.0f / DIM) - mu * mu + EPS);
        #pragma unroll
        for (int j = 0; j < 8; j++) {
            int idx = wid * HD + lane + 32 * j;
            float y = (g[j] - mu) * inv * l2w[idx] + l2b[idx];
            out[(size_t)b * DIM + idx] = gelu_tanh(y);
        }
    }
}

// ---------------- launch ----------------
extern "C" void kernel_launch(void* const* d_in, const int* in_sizes, int n_in,
                              void* d_out, int out_size) {
    const float* f_ad    = (const float*)d_in[0];
    const float* f_age   = (const float*)d_in[1];
    const float* mem     = (const float*)d_in[2];
    const float* age_gap = (const float*)d_in[3];
    const float* qv_W    = (const float*)d_in[4];
    const float* k1_W    = (const float*)d_in[5];
    // d_in[6] = k2_W : dead in the reference — skipped
    const float* ln_w    = (const float*)d_in[7];
    const float* ln_b    = (const float*)d_in[8];
    const float* ln2_w   = (const float*)d_in[9];
    const float* ln2_b   = (const float*)d_in[10];
    const float* agf_rW  = (const float*)d_in[11];
    const float* agf_rb  = (const float*)d_in[12];
    const float* agf_eW  = (const float*)d_in[13];
    const float* agf_eb  = (const float*)d_in[14];
    const float* c1W     = (const float*)d_in[15];
    const float* c2W     = (const float*)d_in[16];
    float* out = (float*)d_out;

    float *qvb, *k1b, *k2n;
    __half *Ahp, *Php;
    cudaGetSymbolAddress((void**)&qvb, g_qv);
    cudaGetSymbolAddress((void**)&k1b, g_k1);
    cudaGetSymbolAddress((void**)&k2n, g_k2n);
    cudaGetSymbolAddress((void**)&Ahp, g_Ah);
    cudaGetSymbolAddress((void**)&Php, g_Ph);

    cudaFuncSetAttribute(gemm_tc, cudaFuncAttributeMaxDynamicSharedMemorySize, GEMM_SMEM);

    // 1) prep: coalesced pool + f_ad cvt + AGF
    prep_kernel<<<NB_PREP, 256>>>(mem, (const float4*)f_ad, f_age, age_gap,
                                  agf_rW, agf_rb, agf_eW, agf_eb, ln_w, ln_b,
                                  Php, Ahp, k2n);
    // 2) GEMM (512 threads / 16 warps per CTA)
    gemm_tc<<<dim3(48, 2), 512, GEMM_SMEM>>>(Ahp, Php, qv_W, k1_W, qvb, k1b);
    // 3) fused head-LN + attention + conv + epilogue
    fused_attn<<<B_SZ, 256>>>(qvb, k1b, k2n, ln_w, ln_b, ln2_w, ln2_b, c1W, c2W, out);
}

// round 13
// speedup vs baseline: 1.2002x; 1.1174x over previous
#include <cuda_runtime.h>
#include <cuda_fp16.h>
#include <math.h>
#include <stdint.h>

#define B_SZ 256
#define DIM 2048
#define NH 8
#define HD 256
#define EPS 1e-5f

// ---------------- scratch (device globals; no allocation allowed) ----------
#define QVP (B_SZ * 2 * DIM)
#define K1P (B_SZ * DIM)
__device__ float g_qvp[3 * QVP];         // split-K partials of qv
__device__ float g_k1p[3 * K1P];         // split-K partials of k1
__device__ float g_k2n[B_SZ * DIM];
__device__ __half g_Ah[B_SZ * DIM];      // f_ad fp16
__device__ __half g_Ph[B_SZ * DIM];      // pooled fp16

// ---------------- helpers ----------------
__device__ __forceinline__ float warp_sum(float v) {
    v += __shfl_xor_sync(0xffffffffu, v, 16);
    v += __shfl_xor_sync(0xffffffffu, v, 8);
    v += __shfl_xor_sync(0xffffffffu, v, 4);
    v += __shfl_xor_sync(0xffffffffu, v, 2);
    v += __shfl_xor_sync(0xffffffffu, v, 1);
    return v;
}

__device__ __forceinline__ float gelu_tanh(float x) {
    const float k = 0.7978845608028654f;
    float x3 = x * x * x;
    return 0.5f * x * (1.0f + tanhf(k * (x + 0.044715f * x3)));
}

__device__ __forceinline__ uint32_t smem_u32(const void* p) {
    uint32_t a;
    asm("{ .reg .u64 t; cvta.to.shared.u64 t, %1; cvt.u32.u64 %0, t; }" : "=r"(a) : "l"(p));
    return a;
}

__device__ __forceinline__ void cpa16(uint32_t dst, const void* src) {
    asm volatile("cp.async.cg.shared.global [%0], [%1], 16;" :: "r"(dst), "l"(src));
}
#define CP_COMMIT() asm volatile("cp.async.commit_group;" ::: "memory")
#define CP_WAIT3()  asm volatile("cp.async.wait_group 3;" ::: "memory")

__device__ __forceinline__ uint32_t pack2h(float a, float b) {
    __half2 h = __floats2half2_rn(a, b);
    return *(uint32_t*)&h;
}

// fp16 mma: D(16x8,f32) += A(16x16,f16) * B(16x8,f16)
__device__ __forceinline__ void mma16816f(float* d, const uint32_t* a, const uint32_t* b) {
    asm volatile(
        "mma.sync.aligned.m16n8k16.row.col.f32.f16.f16.f32 "
        "{%0,%1,%2,%3}, {%4,%5,%6,%7}, {%8,%9}, {%0,%1,%2,%3};"
        : "+f"(d[0]), "+f"(d[1]), "+f"(d[2]), "+f"(d[3])
        : "r"(a[0]), "r"(a[1]), "r"(a[2]), "r"(a[3]), "r"(b[0]), "r"(b[1]));
}

// ---------------- 1) prep: coalesced pool + f_ad cvt + AGF -----------------
#define NB_POOL 8192
#define NB_FAD  128
#define NB_AGF  256
#define NB_PREP (NB_POOL + NB_FAD + NB_AGF)

__global__ void prep_kernel(const float* __restrict__ mem,
                            const float4* __restrict__ f_ad,
                            const float* __restrict__ f_age, const float* __restrict__ age_gap,
                            const float* __restrict__ rW, const float* __restrict__ rb,
                            const float* __restrict__ eW, const float* __restrict__ eb,
                            const float* __restrict__ lw, const float* __restrict__ lb,
                            __half* __restrict__ Ph, __half* __restrict__ Ah,
                            float* __restrict__ k2n) {
    __shared__ float srow[DIM];
    __shared__ float pr[8];
    int bx = blockIdx.x;
    int t = threadIdx.x, wid = t >> 5, lane = t & 31;

    if (bx < NB_POOL) {
        int gwarp = bx * 8 + wid;
        const float4* p = (const float4*)mem + (size_t)gwarp * 128;
        float s[4];
        #pragma unroll
        for (int i = 0; i < 4; i++) {
            float4 v = p[i * 32 + lane];           // fully coalesced 512B per instr
            s[i] = (v.x + v.y) + (v.z + v.w);
        }
        #pragma unroll
        for (int i = 0; i < 4; i++) {
            s[i] += __shfl_xor_sync(0xffffffffu, s[i], 1);
            s[i] += __shfl_xor_sync(0xffffffffu, s[i], 2);
            s[i] += __shfl_xor_sync(0xffffffffu, s[i], 4);
            s[i] += __shfl_xor_sync(0xffffffffu, s[i], 8);
        }
        int half = lane >> 4;
        if ((lane & 15) == 0) {
            #pragma unroll
            for (int i = 0; i < 4; i++)
                Ph[gwarp * 8 + 2 * i + half] = __float2half_rn(s[i] * (1.0f / 64.0f));
        }
        return;
    }
    bx -= NB_POOL;
    if (bx < NB_FAD) {
        int i0 = bx * 1024 + t;
        #pragma unroll
        for (int k = 0; k < 4; k++) {
            int i = i0 + k * 256;
            float4 v = f_ad[i];
            uint2 hp;
            hp.x = pack2h(v.x, v.y);
            hp.y = pack2h(v.z, v.w);
            ((uint2*)Ah)[i] = hp;
        }
        return;
    }
    // AGF branch + per-head LN -> k2_norm; one block per batch row
    int b = bx - NB_FAD;

    float part = 0.f;
    for (int i = t; i < DIM; i += 256) part += f_age[(size_t)b * DIM + i] * rW[i];
    part = warp_sum(part);
    if (lane == 0) pr[wid] = part;
    __syncthreads();
    float red = rb[0];
    #pragma unroll
    for (int i = 0; i < 8; i++) red += pr[i];
    float ag = age_gap[b];

    for (int i = t; i < DIM; i += 256) {
        srow[i] = f_age[(size_t)b * DIM + i] + eW[i * 2 + 0] * red + eW[i * 2 + 1] * ag + eb[i];
    }
    __syncthreads();

    float x[8], s = 0.f, ss = 0.f;
    #pragma unroll
    for (int j = 0; j < 8; j++) {
        x[j] = srow[wid * HD + lane + 32 * j];
        s += x[j]; ss += x[j] * x[j];
    }
    s = warp_sum(s); ss = warp_sum(ss);
    float mu = s * (1.0f / HD);
    float inv = rsqrtf(ss * (1.0f / HD) - mu * mu + EPS);
    #pragma unroll
    for (int j = 0; j < 8; j++) {
        int i = lane + 32 * j;
        k2n[(size_t)b * DIM + wid * HD + i] = (x[j] - mu) * inv * lw[i] + lb[i];
    }
}

// ---------------- 2) GEMM split-K x3: A cp.async 4-stage; B in-loader cvt --
// Partial C[m,n] = sum_{k in split} A[m,k]*W[n,k]. CTA 128x128, chunks of 64.
// grid: x = ntile (0..47), y = mtile (0..1), z = ksplit (0..2: 11/11/10 chunks)
#define PITCH 144
#define TILEB (128 * PITCH)             // 18432
#define NASTAGE 4
#define NBSTAGE 2
#define SMEM_B_OFF (NASTAGE * TILEB)    // 73728
#define GEMM_SMEM (NASTAGE * TILEB + NBSTAGE * TILEB)   // 110592

__global__ void __launch_bounds__(256, 1)
gemm_tc(const __half* __restrict__ Ah, const __half* __restrict__ Ph,
        const float* __restrict__ Wqv, const float* __restrict__ Wk1,
        float* __restrict__ Cqvp, float* __restrict__ Ck1p) {
    extern __shared__ char sm[];
    uint32_t sb = smem_u32(sm);
    int tid = threadIdx.x, wid = tid >> 5, lane = tid & 31;
    int ntile = blockIdx.x, mtile = blockIdx.y, ks_id = blockIdx.z;
    int c0 = ks_id * 11;
    int cnt = (ks_id == 2) ? 10 : 11;

    bool is_qv = ntile < 32;
    const __half* a;
    const float* Wsrc;
    float* C;
    int ldc, ncol0;
    if (is_qv) {
        a = Ah; Wsrc = Wqv + (size_t)ntile * 128 * DIM;
        C = Cqvp + (size_t)ks_id * QVP; ldc = 2 * DIM; ncol0 = ntile * 128;
    } else {
        a = Ph; Wsrc = Wk1 + (size_t)(ntile - 32) * 128 * DIM;
        C = Ck1p + (size_t)ks_id * K1P; ldc = DIM; ncol0 = (ntile - 32) * 128;
    }

    // A loader role: row r, half qp of the 128B fp16 chunk row
    int r = tid >> 1, qp = tid & 1;
    const char* sA = (const char*)(a + (size_t)(mtile * 128 + r) * DIM) + qp * 64;
    uint32_t da = sb + r * PITCH + qp * 64;

    // B loader role: coalesced, 8 float4/thread
    int seg = tid & 15, rb0 = tid >> 4;
    const float4* Wf4 = (const float4*)Wsrc;
    uint32_t dbB[8];
    #pragma unroll
    for (int i = 0; i < 8; i++)
        dbB[i] = sb + SMEM_B_OFF + (uint32_t)(rb0 + 16 * i) * PITCH + seg * 8;

    // compute role
    int warp_m = wid >> 2, warp_n = wid & 3;
    int g = lane >> 2, tig = lane & 3;
    float acc[4][4][4] = {};
    uint32_t fA = sb + (warp_m * 64 + g) * PITCH + tig * 4;
    uint32_t fB0 = sb + SMEM_B_OFF + (warp_n * 32 + g) * PITCH + tig * 4;

    // prologue: B chunk c0 into regs; A stages via cp.async
    float4 b4[8];
    #pragma unroll
    for (int i = 0; i < 8; i++)
        b4[i] = Wf4[(size_t)(rb0 + 16 * i) * 512 + c0 * 16 + seg];
    #pragma unroll
    for (int s = 0; s < NASTAGE; s++) {
        if (s < cnt) {
            uint32_t d = da + s * TILEB;
            const char* pa = sA + (c0 + s) * 128;
            cpa16(d, pa); cpa16(d + 16, pa + 16);
            cpa16(d + 32, pa + 32); cpa16(d + 48, pa + 48);
        }
        CP_COMMIT();
    }

    for (int c = 0; c < cnt; ++c) {
        uint32_t soA = (uint32_t)(c & (NASTAGE - 1)) * TILEB;
        uint32_t soB = (uint32_t)(c & 1) * TILEB;
        CP_WAIT3();
        #pragma unroll
        for (int i = 0; i < 8; i++) {
            uint32_t p0 = pack2h(b4[i].x, b4[i].y);
            uint32_t p1 = pack2h(b4[i].z, b4[i].w);
            asm volatile("st.shared.v2.b32 [%0], {%1,%2};"
                         :: "r"(dbB[i] + soB), "r"(p0), "r"(p1));
        }
        __syncthreads();
        if (c + 1 < cnt) {
            #pragma unroll
            for (int i = 0; i < 8; i++)
                b4[i] = Wf4[(size_t)(rb0 + 16 * i) * 512 + (c0 + c + 1) * 16 + seg];
        }

        #pragma unroll
        for (int ks = 0; ks < 4; ks++) {
            uint32_t kbA = soA + ks * 32;
            uint32_t kbB = soB + ks * 32;
            uint32_t Af[4][4], Bf[4][2];
            #pragma unroll
            for (int i = 0; i < 4; i++) {
                uint32_t ph = fA + i * 16 * PITCH + kbA;
                asm volatile("ld.shared.b32 %0, [%1];" : "=r"(Af[i][0]) : "r"(ph));
                asm volatile("ld.shared.b32 %0, [%1];" : "=r"(Af[i][1]) : "r"(ph + 8 * PITCH));
                asm volatile("ld.shared.b32 %0, [%1];" : "=r"(Af[i][2]) : "r"(ph + 16));
                asm volatile("ld.shared.b32 %0, [%1];" : "=r"(Af[i][3]) : "r"(ph + 8 * PITCH + 16));
            }
            #pragma unroll
            for (int j = 0; j < 4; j++) {
                uint32_t ph = fB0 + j * 8 * PITCH + kbB;
                asm volatile("ld.shared.b32 %0, [%1];" : "=r"(Bf[j][0]) : "r"(ph));
                asm volatile("ld.shared.b32 %0, [%1];" : "=r"(Bf[j][1]) : "r"(ph + 16));
            }
            #pragma unroll
            for (int i = 0; i < 4; i++)
                #pragma unroll
                for (int j = 0; j < 4; j++)
                    mma16816f(acc[i][j], Af[i], Bf[j]);
        }
        __syncthreads();

        int cn = c + NASTAGE;
        if (cn < cnt) {
            uint32_t d = da + soA;
            const char* pa = sA + (c0 + cn) * 128;
            cpa16(d, pa); cpa16(d + 16, pa + 16);
            cpa16(d + 32, pa + 32); cpa16(d + 48, pa + 48);
        }
        CP_COMMIT();
    }

    // epilogue: write this split's partial
    #pragma unroll
    for (int i = 0; i < 4; i++) {
        int r0 = mtile * 128 + warp_m * 64 + i * 16 + g;
        #pragma unroll
        for (int j = 0; j < 4; j++) {
            int col = ncol0 + warp_n * 32 + j * 8 + 2 * tig;
            *(float2*)&C[(size_t)r0 * ldc + col]       = make_float2(acc[i][j][0], acc[i][j][1]);
            *(float2*)&C[(size_t)(r0 + 8) * ldc + col] = make_float2(acc[i][j][2], acc[i][j][3]);
        }
    }
}

// ---------------- 3) fused: 3-way reduce + head-LN + attn + conv + epilogue
__global__ void __launch_bounds__(256, 4)
fused_attn(const float* __restrict__ qvp, const float* __restrict__ k1p,
           const float* __restrict__ k2n,
           const float* __restrict__ lw, const float* __restrict__ lb,
           const float* __restrict__ l2w, const float* __restrict__ l2b,
           const float* __restrict__ w1, const float* __restrict__ w2,
           float* __restrict__ out) {
    __shared__ float sQ[DIM], sK1[DIM], sK2[DIM], sV[DIM], sO1[DIM];
    __shared__ float cw1[192], cw2[192];
    __shared__ float rs[8], rss[8];
    float* sO2 = sK1;

    int b = blockIdx.x, t = threadIdx.x;
    int wid = t >> 5, lane = t & 31;

    // per-head LN of q (sum of 3 split-K partials), each warp = one head
    {
        float x[8], s = 0.f, ss = 0.f;
        #pragma unroll
        for (int j = 0; j < 8; j++) {
            size_t idx = (size_t)b * 2 * DIM + wid * HD + lane + 32 * j;
            x[j] = qvp[idx] + qvp[idx + QVP] + qvp[idx + 2 * QVP];
            s += x[j]; ss += x[j] * x[j];
        }
        s = warp_sum(s); ss = warp_sum(ss);
        float mu = s * (1.0f / HD), inv = rsqrtf(ss * (1.0f / HD) - mu * mu + EPS);
        #pragma unroll
        for (int j = 0; j < 8; j++) {
            int i = lane + 32 * j;
            sQ[wid * HD + i] = (x[j] - mu) * inv * lw[i] + lb[i];
        }
    }
    // per-head LN of k1 (sum of 3 partials)
    {
        float x[8], s = 0.f, ss = 0.f;
        #pragma unroll
        for (int j = 0; j < 8; j++) {
            size_t idx = (size_t)b * DIM + wid * HD + lane + 32 * j;
            x[j] = k1p[idx] + k1p[idx + K1P] + k1p[idx + 2 * K1P];
            s += x[j]; ss += x[j] * x[j];
        }
        s = warp_sum(s); ss = warp_sum(ss);
        float mu = s * (1.0f / HD), inv = rsqrtf(ss * (1.0f / HD) - mu * mu + EPS);
        #pragma unroll
        for (int j = 0; j < 8; j++) {
            int i = lane + 32 * j;
            sK1[wid * HD + i] = (x[j] - mu) * inv * lw[i] + lb[i];
        }
    }
    // v (sum of 3 partials) + k2n
    for (int i = t; i < DIM; i += 256) {
        sK2[i] = k2n[(size_t)b * DIM + i];
        size_t vi = (size_t)b * 2 * DIM + DIM + i;
        sV[i] = qvp[vi] + qvp[vi + QVP] + qvp[vi + 2 * QVP];
    }
    if (t < 192) { cw1[t] = w1[t]; cw2[t] = w2[t]; }
    __syncthreads();

    {
        float a[8];
        #pragma unroll
        for (int s = 0; s < 8; s++) {
            float p = 0.f;
            #pragma unroll
            for (int j = 0; j < 8; j++)
                p = fmaf(sQ[wid * HD + lane + 32 * j], sK1[s * HD + lane + 32 * j], p);
            a[s] = warp_sum(p) * (1.0f / 16.0f);
        }
        float m = a[0];
        #pragma unroll
        for (int s = 1; s < 8; s++) m = fmaxf(m, a[s]);
        float sum = 0.f;
        #pragma unroll
        for (int s = 0; s < 8; s++) { a[s] = expf(a[s] - m); sum += a[s]; }
        float inv = 1.0f / sum;
        #pragma unroll
        for (int j = 0; j < 8; j++) {
            int cc = lane + 32 * j;
            float acc = 0.f;
            #pragma unroll
            for (int s = 0; s < 8; s++) acc = fmaf(a[s], sV[s * HD + cc], acc);
            sO1[wid * HD + cc] = acc * inv;
        }
    }
    __syncthreads();

    {
        float a[8];
        #pragma unroll
        for (int s = 0; s < 8; s++) {
            float p = 0.f;
            #pragma unroll
            for (int j = 0; j < 8; j++)
                p = fmaf(sQ[wid * HD + lane + 32 * j], sK2[s * HD + lane + 32 * j], p);
            a[s] = warp_sum(p) * (1.0f / 16.0f);
        }
        float m = a[0];
        #pragma unroll
        for (int s = 1; s < 8; s++) m = fmaxf(m, a[s]);
        float sum = 0.f;
        #pragma unroll
        for (int s = 0; s < 8; s++) { a[s] = expf(a[s] - m); sum += a[s]; }
        float inv = 1.0f / sum;
        #pragma unroll
        for (int j = 0; j < 8; j++) {
            int cc = lane + 32 * j;
            float acc = 0.f;
            #pragma unroll
            for (int s = 0; s < 8; s++) acc = fmaf(a[s], sV[s * HD + cc], acc);
            sO2[wid * HD + cc] = acc * inv;
        }
    }
    __syncthreads();

    float c1[8], c2[8], g[8];
    #pragma unroll
    for (int j = 0; j < 8; j++) {
        int l = lane + 32 * j;
        float a1 = 0.f, a2 = 0.f;
        #pragma unroll
        for (int i = 0; i < 8; i++) {
            float xm = (l > 0)   ? sO1[i * HD + l - 1] : 0.f;
            float x0 =             sO1[i * HD + l];
            float xp = (l < 255) ? sO1[i * HD + l + 1] : 0.f;
            a1 = fmaf(cw1[wid * 24 + i * 3 + 0], xm, a1);
            a1 = fmaf(cw1[wid * 24 + i * 3 + 1], x0, a1);
            a1 = fmaf(cw1[wid * 24 + i * 3 + 2], xp, a1);
            float ym = (l > 0)   ? sO2[i * HD + l - 1] : 0.f;
            float y0 =             sO2[i * HD + l];
            float yp = (l < 255) ? sO2[i * HD + l + 1] : 0.f;
            a2 = fmaf(cw2[wid * 24 + i * 3 + 0], ym, a2);
            a2 = fmaf(cw2[wid * 24 + i * 3 + 1], y0, a2);
            a2 = fmaf(cw2[wid * 24 + i * 3 + 2], yp, a2);
        }
        c1[j] = a1; c2[j] = a2;
    }

    {
        float s = 0.f, ss = 0.f;
        #pragma unroll
        for (int j = 0; j < 8; j++) { s += c1[j]; ss += c1[j] * c1[j]; }
        s = warp_sum(s); ss = warp_sum(ss);
        float mu = s * (1.0f / HD), inv = rsqrtf(ss * (1.0f / HD) - mu * mu + EPS);
        #pragma unroll
        for (int j = 0; j < 8; j++) { int i = lane + 32 * j; c1[j] = (c1[j] - mu) * inv * lw[i] + lb[i]; }
    }
    {
        float s = 0.f, ss = 0.f;
        #pragma unroll
        for (int j = 0; j < 8; j++) { s += c2[j]; ss += c2[j] * c2[j]; }
        s = warp_sum(s); ss = warp_sum(ss);
        float mu = s * (1.0f / HD), inv = rsqrtf(ss * (1.0f / HD) - mu * mu + EPS);
        #pragma unroll
        for (int j = 0; j < 8; j++) { int i = lane + 32 * j; c2[j] = (c2[j] - mu) * inv * lw[i] + lb[i]; }
    }
    {
        float x[8], s = 0.f, ss = 0.f;
        #pragma unroll
        for (int j = 0; j < 8; j++) {
            x[j] = c1[j] + c2[j] + sV[wid * HD + lane + 32 * j];
            s += x[j]; ss += x[j] * x[j];
        }
        s = warp_sum(s); ss = warp_sum(ss);
        float mu = s * (1.0f / HD), inv = rsqrtf(ss * (1.0f / HD) - mu * mu + EPS);
        #pragma unroll
        for (int j = 0; j < 8; j++) {
            int i = lane + 32 * j;
            g[j] = gelu_tanh((x[j] - mu) * inv * lw[i] + lb[i]);
        }
    }
    {
        float s = 0.f, ss = 0.f;
        #pragma unroll
        for (int j = 0; j < 8; j++) { s += g[j]; ss += g[j] * g[j]; }
        s = warp_sum(s); ss = warp_sum(ss);
        if (lane == 0) { rs[wid] = s; rss[wid] = ss; }
        __syncthreads();
        float ts = 0.f, tss = 0.f;
        #pragma unroll
        for (int i = 0; i < 8; i++) { ts += rs[i]; tss += rss[i]; }
        float mu = ts * (1.0f / DIM), inv = rsqrtf(tss * (1.0f / DIM) - mu * mu + EPS);
        #pragma unroll
        for (int j = 0; j < 8; j++) {
            int idx = wid * HD + lane + 32 * j;
            float y = (g[j] - mu) * inv * l2w[idx] + l2b[idx];
            out[(size_t)b * DIM + idx] = gelu_tanh(y);
        }
    }
}

// ---------------- launch ----------------
extern "C" void kernel_launch(void* const* d_in, const int* in_sizes, int n_in,
                              void* d_out, int out_size) {
    const float* f_ad    = (const float*)d_in[0];
    const float* f_age   = (const float*)d_in[1];
    const float* mem     = (const float*)d_in[2];
    const float* age_gap = (const float*)d_in[3];
    const float* qv_W    = (const float*)d_in[4];
    const float* k1_W    = (const float*)d_in[5];
    // d_in[6] = k2_W : dead in the reference — skipped
    const float* ln_w    = (const float*)d_in[7];
    const float* ln_b    = (const float*)d_in[8];
    const float* ln2_w   = (const float*)d_in[9];
    const float* ln2_b   = (const float*)d_in[10];
    const float* agf_rW  = (const float*)d_in[11];
    const float* agf_rb  = (const float*)d_in[12];
    const float* agf_eW  = (const float*)d_in[13];
    const float* agf_eb  = (const float*)d_in[14];
    const float* c1W     = (const float*)d_in[15];
    const float* c2W     = (const float*)d_in[16];
    float* out = (float*)d_out;

    float *qvp, *k1p, *k2n;
    __half *Ahp, *Php;
    cudaGetSymbolAddress((void**)&qvp, g_qvp);
    cudaGetSymbolAddress((void**)&k1p, g_k1p);
    cudaGetSymbolAddress((void**)&k2n, g_k2n);
    cudaGetSymbolAddress((void**)&Ahp, g_Ah);
    cudaGetSymbolAddress((void**)&Php, g_Ph);

    cudaFuncSetAttribute(gemm_tc, cudaFuncAttributeMaxDynamicSharedMemorySize, GEMM_SMEM);

    // 1) prep: coalesced pool + f_ad cvt + AGF
    prep_kernel<<<NB_PREP, 256>>>(mem, (const float4*)f_ad, f_age, age_gap,
                                  agf_rW, agf_rb, agf_eW, agf_eb, ln_w, ln_b,
                                  Php, Ahp, k2n);
    // 2) GEMM split-K x3 over 288 CTAs (2 nearly-full waves)
    gemm_tc<<<dim3(48, 2, 3), 256, GEMM_SMEM>>>(Ahp, Php, qv_W, k1_W, qvp, k1p);
    // 3) fused 3-way reduce + head-LN + attention + conv + epilogue
    fused_attn<<<B_SZ, 256>>>(qvp, k1p, k2n, ln_w, ln_b, ln2_w, ln2_b, c1W, c2W, out);
}